// round 13
// baseline (speedup 1.0000x reference)
#include <cuda_runtime.h>
#include <stdint.h>

#define LL 401
#define BB 256
#define PLANE 160801             // LL*LL
#define TOTELEM (BB * PLANE)     // 41,165,056 (divisible by 4)
#define PROWS 48                 // rows per panel
#define NPANEL 9                 // ceil(401/48)
#define NBLK (BB * NPANEL)       // 2304
#define TPB 128
#define RCH 4                    // rows per chunk (= warps per block)
#define NSLOT 4                  // ring depth (3 copies in flight)
#define BUFN 1612                // floats per buffer (3 + 4*401 = 1607, pad to 16B mult)

// ---------------- device-global scratch (no allocations allowed) -------------
__device__ double g_bin[LL];
__device__ double g_W;
__device__ double g_NC;
__device__ double g_bSame[BB];
__device__ double g_bNc[BB];
__device__ unsigned char g_P[BB * LL + 64];  // bit0=comp b1=any b2=f b3=r (+pad)
__device__ unsigned g_done;

// ---------------- mbarrier / bulk-copy PTX ----------------------------------
__device__ __forceinline__ unsigned smem_u32(const void* p) {
    return (unsigned)__cvta_generic_to_shared(p);
}
__device__ __forceinline__ void mbar_init(unsigned a, unsigned cnt) {
    asm volatile("mbarrier.init.shared.b64 [%0], %1;" :: "r"(a), "r"(cnt) : "memory");
}
__device__ __forceinline__ void mbar_expect_tx(unsigned a, unsigned tx) {
    asm volatile("mbarrier.arrive.expect_tx.shared.b64 _, [%0], %1;" :: "r"(a), "r"(tx) : "memory");
}
__device__ __forceinline__ void bulk_g2s(unsigned dst, const void* src, unsigned bytes, unsigned mbar) {
    asm volatile("cp.async.bulk.shared::cluster.global.mbarrier::complete_tx::bytes [%0], [%1], %2, [%3];"
                 :: "r"(dst), "l"(src), "r"(bytes), "r"(mbar) : "memory");
}
__device__ __forceinline__ void mbar_wait(unsigned a, unsigned parity) {
    asm volatile("{\n\t.reg .pred P1;\n\t"
                 "WL_%=:\n\t"
                 "mbarrier.try_wait.parity.acquire.cta.shared::cta.b64 P1, [%0], %1, 0x989680;\n\t"
                 "@P1 bra.uni WD_%=;\n\t"
                 "bra.uni WL_%=;\n\t"
                 "WD_%=:\n\t}"
                 :: "r"(a), "r"(parity) : "memory");
}
__device__ __forceinline__ void fence_proxy_async_cta() {
    asm volatile("fence.proxy.async.shared::cta;" ::: "memory");
}

// ---------------- prep: pack bytes + per-batch counts + zero globals ---------
__global__ void k_prep(const float2* __restrict__ logits, const int* __restrict__ ctcf) {
    int b = blockIdx.x, t = threadIdx.x;
    if (b == 0) {
        if (t < LL) g_bin[t] = 0.0;
        if (t == LL) { g_W = 0.0; g_NC = 0.0; }
    }
    __shared__ unsigned char sc[LL];
    __shared__ unsigned long long shw[16];
    unsigned long long pack = 0ull;
    if (t < LL) {
        int idx = b * LL + t;
        float2 l = logits[idx];
        int o = ctcf[idx];
        unsigned c = (l.y > l.x) ? 1u : 0u;
        unsigned A = (o != 0) ? 1u : 0u;
        unsigned F = (o == 1) ? 1u : 0u;
        unsigned R = (o == -1) ? 1u : 0u;
        g_P[idx] = (unsigned char)(c | (A << 1) | (F << 2) | (R << 3));
        sc[t] = (unsigned char)c;
        pack = (unsigned long long)c
             | ((unsigned long long)F << 24)
             | ((unsigned long long)R << 36)
             | ((unsigned long long)A << 48);
    }
    __syncthreads();
    if (t < LL - 1) pack |= ((unsigned long long)(sc[t] == sc[t + 1] ? 1u : 0u)) << 12;

#pragma unroll
    for (int o = 16; o > 0; o >>= 1) pack += __shfl_down_sync(0xffffffffu, pack, o);
    if ((t & 31) == 0) shw[t >> 5] = pack;
    __syncthreads();
    if (t == 0) {
        unsigned long long s = 0;
        for (int w = 0; w < 16; w++) s += shw[w];
        double n1  = (double)(s & 0xFFFull);
        double adj = (double)((s >> 12) & 0xFFFull);
        double F   = (double)((s >> 24) & 0xFFFull);
        double R   = (double)((s >> 36) & 0xFFFull);
        double A   = (double)((s >> 48) & 0xFFFull);
        double n0  = (double)LL - n1;
        g_bSame[b] = n0 * n0 + n1 * n1 - (double)LL - 2.0 * adj;
        g_bNc[b]   = A * A - F * R;
    }
}

// ---------------- block reduction over 128 threads --------------------------
__device__ __forceinline__ double bred128(double v, double* sh) {
    int t = threadIdx.x;
#pragma unroll
    for (int o = 16; o > 0; o >>= 1) v += __shfl_down_sync(0xffffffffu, v, o);
    if ((t & 31) == 0) sh[t >> 5] = v;
    __syncthreads();
    if (t == 0) sh[0] = sh[0] + sh[1] + sh[2] + sh[3];
    __syncthreads();
    double r = sh[0];
    __syncthreads();
    return r;
}

// ---------------- main pass: deep-pipelined bulk-copy + diagonal bins --------
__global__ void __launch_bounds__(TPB, 5) k_main(const float* __restrict__ cm,
                                                 float* __restrict__ out) {
    __shared__ __align__(16) float s_buf[NSLOT][BUFN];
    __shared__ float s_bin[RCH][802];
    __shared__ unsigned long long s_mbar[NSLOT];
    __shared__ double s_red[4];
    __shared__ double sW[4], sN[4];

    int tid = threadIdx.x;
    int w = tid >> 5, lane = tid & 31;
    int b = blockIdx.x;
    int r0 = blockIdx.y * PROWS;
    int r1 = min(LL, r0 + PROWS);
    int nch = (r1 - r0 + RCH - 1) / RCH;

    unsigned mb[NSLOT];
#pragma unroll
    for (int s = 0; s < NSLOT; s++) mb[s] = smem_u32(&s_mbar[s]);

    for (int k = tid; k < RCH * 802; k += TPB) ((float*)s_bin)[k] = 0.f;
    if (tid == 0) {
#pragma unroll
        for (int s = 0; s < NSLOT; s++) mbar_init(mb[s], 1);
        fence_proxy_async_cta();
    }
    __syncthreads();

    // per-lane cj bytes for this plane: columns lane+32c, c=0..12
    const unsigned char* pb = g_P + b * LL;
    unsigned cjp[4] = {0, 0, 0, 0};
#pragma unroll
    for (int c = 0; c < 13; c++)
        cjp[c >> 2] |= (unsigned)pb[32 * c + lane] << (8 * (c & 3));

    auto issue = [&](int c) {
        int i0c = r0 + c * RCH;
        int rows = min(RCH, r1 - i0c);
        long long gstart = (long long)b * PLANE + (long long)i0c * LL;
        long long galign = gstart & ~3ll;
        int off = (int)(gstart - galign);
        int nfl = (off + rows * LL + 3) & ~3;
        if (galign + nfl > (long long)TOTELEM) nfl = (int)((long long)TOTELEM - galign);
        unsigned bytes = (unsigned)nfl * 4u;
        unsigned m = mb[c & (NSLOT - 1)];
        mbar_expect_tx(m, bytes);
        bulk_g2s(smem_u32(&s_buf[c & (NSLOT - 1)][0]), cm + galign, bytes, m);
    };

    if (tid == 0) {
        for (int c = 0; c < 3 && c < nch; c++) issue(c);
    }

    float accW = 0.f, accNC = 0.f;
    float* mybin = s_bin[w];

    for (int c = 0; c < nch; c++) {
        mbar_wait(mb[c & (NSLOT - 1)], (c >> 2) & 1);
        // issue next copy IMMEDIATELY (slot (c+3)&3 was consumed at c-1, synced)
        if (tid == 0 && c + 3 < nch) issue(c + 3);

        int i0c = r0 + c * RCH;
        int i = i0c + w;
        if (i < r1) {
            int off = (int)(((long long)b * PLANE + (long long)i0c * LL) & 3);
            const float* rb = &s_buf[c & (NSLOT - 1)][off + w * LL];
            unsigned ci = pb[i];

            // per-row masks: wm bit c = same-comp & maskf ; nm bit c = non-conv pair
            unsigned cid = ci * 0x01010101u;
            unsigned rselB = (ci & 4u) ? 0x08080808u : 0u;
            unsigned wm = 0, nm = 0;
#pragma unroll
            for (int q = 0; q < 4; q++) {
                unsigned same = ~(cjp[q] ^ cid) & 0x01010101u;
                wm |= (((same * 0x01020408u) >> 24) & 0xFu) << (4 * q);
                unsigned nc_ = (cjp[q] & 0x02020202u) & ~((cjp[q] & rselB) >> 2);
                nm |= (((((nc_ >> 1) & 0x01010101u) * 0x01020408u) >> 24) & 0xFu) << (4 * q);
            }
            nm = (ci & 2u) ? nm : 0u;
#pragma unroll
            for (int dj = -1; dj <= 1; dj++) {
                int t = i + dj - lane;
                if (t >= 0 && (t & 31) == 0) wm &= ~(1u << (t >> 5));
            }

            float* bA = mybin + (i + 400 - lane);
#pragma unroll
            for (int cc = 0; cc < 12; cc++) {
                float vv = rb[32 * cc + lane];
                bA[-32 * cc] += vv;                          // conflict-free RMW
                if ((wm >> cc) & 1u) accW += vv;
                if ((nm >> cc) & 1u) accNC += fmaxf(vv, 0.f);
            }
            if (lane < 17) {
                float vv = rb[384 + lane];
                bA[-384] += vv;
                if ((wm >> 12) & 1u) accW += vv;
                if ((nm >> 12) & 1u) accNC += fmaxf(vv, 0.f);
            }
        }
        __syncthreads();                                     // slot c free for c+4
    }

    // fold per-warp signed-diagonal bins -> g_bin
    __syncthreads();
    for (int t = tid; t < LL; t += TPB) {
        float s = 0.f;
#pragma unroll
        for (int q = 0; q < RCH; q++) {
            s += s_bin[q][400 + t];
            if (t) s += s_bin[q][400 - t];
        }
        atomicAdd(&g_bin[t], (double)s);
    }

    // scalar reductions -> 2 double atomics per block
#pragma unroll
    for (int o = 16; o > 0; o >>= 1) {
        accW  += __shfl_down_sync(0xffffffffu, accW,  o);
        accNC += __shfl_down_sync(0xffffffffu, accNC, o);
    }
    if (lane == 0) { sW[w] = accW; sN[w] = accNC; }
    __syncthreads();
    if (tid == 0) {
        double ww = sW[0] + sW[1] + sW[2] + sW[3];
        double nn = sN[0] + sN[1] + sN[2] + sN[3];
        atomicAdd(&g_W, ww);
        atomicAdd(&g_NC, nn);
    }

    // ---------- last-block-done: fused finalize ----------
    __shared__ bool isLast;
    __threadfence();
    if (tid == 0) {
        unsigned v0 = atomicAdd(&g_done, 1u);
        isLast = (v0 == (unsigned)(NBLK - 1));
    }
    __syncthreads();
    if (!isLast) return;
    if (tid == 0) g_done = 0;
    __threadfence();

    {
        double n = 0, sx = 0, sy = 0, tm = 0, sameC = 0, ncC = 0;
#pragma unroll
        for (int k = 0; k < 4; k++) {
            int t = tid + TPB * k;
            if (t < LL) {
                double bs = g_bin[t];
                double cnt = (t == 0) ? (double)LL : 2.0 * (double)(LL - t);
                double mean = bs / (cnt * (double)BB);
                bool va = (t >= 2) && isfinite(mean) && (mean > 0.0);
                double wv = va ? 1.0 : 0.0;
                double ld = log(fmax((double)t, 1.0));
                double lp = log((va ? mean : 1.0) + 1e-6);
                n += wv; sx += wv * ld; sy += wv * lp;
                if (t >= 2) tm += bs;
            }
            if (t < BB) { sameC += g_bSame[t]; ncC += g_bNc[t]; }
        }
        n = bred128(n, s_red);
        sx = bred128(sx, s_red);
        sy = bred128(sy, s_red);
        tm = bred128(tm, s_red);
        sameC = bred128(sameC, s_red);
        ncC = bred128(ncC, s_red);

        double nsafe = fmax(n, 1.0);
        double xm = sx / nsafe, ym = sy / nsafe;
        double num = 0, den = 0;
#pragma unroll
        for (int k = 0; k < 4; k++) {
            int t = tid + TPB * k;
            if (t < LL) {
                double bs = g_bin[t];
                double cnt = (t == 0) ? (double)LL : 2.0 * (double)(LL - t);
                double mean = bs / (cnt * (double)BB);
                bool va = (t >= 2) && isfinite(mean) && (mean > 0.0);
                double wv = va ? 1.0 : 0.0;
                double ld = log(fmax((double)t, 1.0));
                double lp = log((va ? mean : 1.0) + 1e-6);
                num += wv * (ld - xm) * (lp - ym);
                den += wv * (ld - xm) * (ld - xm);
            }
        }
        num = bred128(num, s_red);
        den = bred128(den, s_red) + 1e-8;

        if (tid == 0) {
            double slope = num / den;
            double dist  = (n >= 5.0) ? (slope + 0.85) * (slope + 0.85) : 0.0;

            double ctcf = (ncC < 1.0) ? 0.0 : g_NC / (ncC + 1e-6);

            double diffC   = (double)BB * ((double)LL * LL - 3.0 * LL + 2.0) - sameC;
            double within  = g_W / fmax(sameC, 1.0);
            double between = (tm - g_W) / fmax(diffC, 1.0);
            double ratio   = within / (fabs(between) + 1e-6);
            double comp    = fmax(0.0, 1.5 - ratio);

            out[0] = (float)dist;
            out[1] = (float)ctcf;
            out[2] = (float)comp;
            out[3] = (float)(dist + 0.5 * ctcf + 0.5 * comp);
        }
    }
}

// ---------------- launch ----------------------------------------------------
extern "C" void kernel_launch(void* const* d_in, const int* in_sizes, int n_in,
                              void* d_out, int out_size) {
    const float* cm      = (const float*)d_in[0];
    const float2* logits = (const float2*)d_in[1];
    const int*   ctcf    = (const int*)d_in[2];
    float* out = (float*)d_out;

    k_prep<<<BB, 512>>>(logits, ctcf);
    k_main<<<dim3(BB, NPANEL), TPB>>>(cm, out);
}

// round 14
// speedup vs baseline: 1.1260x; 1.1260x over previous
#include <cuda_runtime.h>
#include <stdint.h>

#define LL 401
#define BB 256
#define PLANE 160801             // LL*LL
#define PROWS 51                 // rows per panel
#define NPANEL 8                 // ceil(401/51)
#define NBLK (BB * NPANEL)       // 2048
#define BRES 184                 // planes pinned L2-resident (~118 MB of 126 MB L2)

// ---------------- device-global scratch (no allocations allowed) -------------
__device__ double g_bin[LL];             // per-distance-bin sum of cm
__device__ double g_W;                   // sum cm * same * maskf
__device__ double g_NC;                  // sum relu(cm) * non_conv
__device__ double g_bSame[BB];           // per-batch same*maskf count
__device__ double g_bNc[BB];             // per-batch non_conv count
__device__ unsigned char g_P[BB * LL + 64]; // [b*401+pos] bit0=comp b1=any b2=f b3=r (+pad)
__device__ unsigned g_done;              // last-block-done counter

// ---------------- cache-policy load helpers ----------------------------------
__device__ __forceinline__ float ldg_pol(const float* p, unsigned long long pol) {
    float v;
    asm volatile("ld.global.nc.L2::cache_hint.f32 %0, [%1], %2;"
                 : "=f"(v) : "l"(p), "l"(pol));
    return v;
}

// ---------------- prep: pack bytes + per-batch counts + zero globals ---------
__global__ void k_prep(const float2* __restrict__ logits, const int* __restrict__ ctcf) {
    int b = blockIdx.x, t = threadIdx.x;
    if (b == 0) {                         // zero accumulators (graph is replayed)
        if (t < LL) g_bin[t] = 0.0;
        if (t == LL) { g_W = 0.0; g_NC = 0.0; }
    }
    __shared__ unsigned char sc[LL];
    __shared__ unsigned long long shw[16];
    unsigned long long pack = 0ull;
    if (t < LL) {
        int idx = b * LL + t;
        float2 l = logits[idx];
        int o = ctcf[idx];
        unsigned c = (l.y > l.x) ? 1u : 0u;      // argmax of 2 logits (tie -> 0)
        unsigned A = (o != 0) ? 1u : 0u;
        unsigned F = (o == 1) ? 1u : 0u;
        unsigned R = (o == -1) ? 1u : 0u;
        g_P[idx] = (unsigned char)(c | (A << 1) | (F << 2) | (R << 3));
        sc[t] = (unsigned char)c;
        pack = (unsigned long long)c
             | ((unsigned long long)F << 24)
             | ((unsigned long long)R << 36)
             | ((unsigned long long)A << 48);
    }
    __syncthreads();
    if (t < LL - 1) pack |= ((unsigned long long)(sc[t] == sc[t + 1] ? 1u : 0u)) << 12;

#pragma unroll
    for (int o = 16; o > 0; o >>= 1) pack += __shfl_down_sync(0xffffffffu, pack, o);
    if ((t & 31) == 0) shw[t >> 5] = pack;
    __syncthreads();
    if (t == 0) {
        unsigned long long s = 0;
        for (int w = 0; w < 16; w++) s += shw[w];
        double n1  = (double)(s & 0xFFFull);
        double adj = (double)((s >> 12) & 0xFFFull);
        double F   = (double)((s >> 24) & 0xFFFull);
        double R   = (double)((s >> 36) & 0xFFFull);
        double A   = (double)((s >> 48) & 0xFFFull);
        double n0  = (double)LL - n1;
        g_bSame[b] = n0 * n0 + n1 * n1 - (double)LL - 2.0 * adj;  // same & |i-j|>=2
        g_bNc[b]   = A * A - F * R;                               // non_conv count
    }
}

// ---------------- block reduction over 256 threads --------------------------
__device__ __forceinline__ double blockRed256(double v, double* sh) {
    int t = threadIdx.x;
#pragma unroll
    for (int o = 16; o > 0; o >>= 1) v += __shfl_down_sync(0xffffffffu, v, o);
    if ((t & 31) == 0) sh[t >> 5] = v;
    __syncthreads();
    double r;
    if (t < 32) {
        double w = (t < 8) ? sh[t] : 0.0;
#pragma unroll
        for (int o = 4; o > 0; o >>= 1) w += __shfl_down_sync(0xffffffffu, w, o);
        if (t == 0) sh[0] = w;
    }
    __syncthreads();
    r = sh[0];
    __syncthreads();
    return r;
}

// ---------------- main pass: streaming rows + signed-diagonal smem bins ------
__global__ void __launch_bounds__(256, 5) k_main(const float* __restrict__ cm,
                                                 float* __restrict__ out) {
    __shared__ float sb[8][802];          // per-warp signed-diagonal bins (25.7 KB)
    int tid = threadIdx.x;
    int w = tid >> 5, lane = tid & 31;
    int b = blockIdx.x;                   // plane
    int r0 = blockIdx.y * PROWS;
    int r1 = min(LL, r0 + PROWS);

    // L2 policy: resident planes -> evict_last; streaming planes -> evict_first
    unsigned long long polL, polF;
    asm("createpolicy.fractional.L2::evict_last.b64 %0, 1.0;"  : "=l"(polL));
    asm("createpolicy.fractional.L2::evict_first.b64 %0, 1.0;" : "=l"(polF));
    unsigned long long pol = (b < BRES) ? polL : polF;

    // zero per-warp bin arrays
    for (int k = tid; k < 8 * 802; k += 256) ((float*)sb)[k] = 0.f;

    // preload this block's cj bytes: column lane+32c of plane b, c=0..12 (pad-safe)
    const unsigned char* pb = g_P + b * LL;
    unsigned cjp[4] = {0, 0, 0, 0};
#pragma unroll
    for (int c = 0; c < 13; c++)
        cjp[c >> 2] |= (unsigned)pb[32 * c + lane] << (8 * (c & 3));
    __syncthreads();

    float accW = 0.f, accNC = 0.f;
    float* mybin = sb[w];
    const float* rowp = cm + (size_t)b * PLANE + (size_t)(r0 + w) * LL;

    for (int i = r0 + w; i < r1; i += 8, rowp += 8 * LL) {
        unsigned ci = pb[i];
        float v[12];
#pragma unroll
        for (int c = 0; c < 12; c++) v[c] = ldg_pol(rowp + 32 * c + lane, pol);
        float tv = (lane < 17) ? ldg_pol(rowp + 384 + lane, pol) : 0.f;
        float* A = mybin + (i + 400 - lane);

#pragma unroll
        for (int c = 0; c < 12; c++) {
            float vv = v[c];
            unsigned cj = (cjp[c >> 2] >> (8 * (c & 3))) & 0xFFu;
            A[-32 * c] += vv;                                      // conflict-free RMW
            int tt = i - 32 * c - lane;                            // i - j
            bool wok = ((unsigned)(tt + 1) > 2u);                  // |i-j| >= 2
            if (wok && !((ci ^ cj) & 1u)) accW += vv;
            if (((ci & cj & 2u) != 0u) && !(((ci & 4u) != 0u) && ((cj & 8u) != 0u)))
                accNC += fmaxf(vv, 0.f);
        }
        // tail chunk j = 384 + lane, active lanes < 17
        if (lane < 17) {
            unsigned cj = (cjp[3]) & 0xFFu;                        // c=12 -> byte 0 of word 3
            A[-384] += tv;
            int tt = i - 384 - lane;
            bool wok = ((unsigned)(tt + 1) > 2u);
            if (wok && !((ci ^ cj) & 1u)) accW += tv;
            if (((ci & cj & 2u) != 0u) && !(((ci & 4u) != 0u) && ((cj & 8u) != 0u)))
                accNC += fmaxf(tv, 0.f);
        }
    }

    __syncthreads();
    // fold per-warp signed bins -> g_bin[d] (d and -d)
    for (int t = tid; t < LL; t += 256) {
        float s = 0.f;
#pragma unroll
        for (int q = 0; q < 8; q++) {
            s += sb[q][400 + t];
            if (t) s += sb[q][400 - t];
        }
        atomicAdd(&g_bin[t], (double)s);
    }

    // scalar reductions -> 2 double atomics per block
#pragma unroll
    for (int o = 16; o > 0; o >>= 1) {
        accW  += __shfl_down_sync(0xffffffffu, accW,  o);
        accNC += __shfl_down_sync(0xffffffffu, accNC, o);
    }
    __shared__ double sW[8], sN[8];
    if ((tid & 31) == 0) { sW[tid >> 5] = accW; sN[tid >> 5] = accNC; }
    __syncthreads();
    if (tid == 0) {
        double ww = 0.0, nn = 0.0;
#pragma unroll
        for (int z = 0; z < 8; z++) { ww += sW[z]; nn += sN[z]; }
        atomicAdd(&g_W, ww);
        atomicAdd(&g_NC, nn);
    }

    // ---------- last-block-done: fused finalize ----------
    __shared__ bool isLast;
    __threadfence();
    if (tid == 0) {
        unsigned v0 = atomicAdd(&g_done, 1u);
        isLast = (v0 == (unsigned)(NBLK - 1));
    }
    __syncthreads();
    if (!isLast) return;
    if (tid == 0) g_done = 0;            // reset for next graph replay
    __threadfence();

    {
        __shared__ double sh[8];
        int t = tid;
        int t1 = t + 256;

        double bs0 = (t  < LL) ? g_bin[t]  : 0.0;
        double bs1 = (t1 < LL) ? g_bin[t1] : 0.0;
        double cnt0 = (t == 0) ? (double)LL : 2.0 * (double)(LL - t);
        double cnt1 = 2.0 * (double)(LL - t1);
        double mean0 = bs0 / (cnt0 * (double)BB);
        double mean1 = (t1 < LL) ? bs1 / (cnt1 * (double)BB) : 0.0;
        bool va0 = (t  < LL) && (t  >= 2) && isfinite(mean0) && (mean0 > 0.0);
        bool va1 = (t1 < LL)              && isfinite(mean1) && (mean1 > 0.0);
        double w0 = va0 ? 1.0 : 0.0, w1 = va1 ? 1.0 : 0.0;
        double ld0 = log(fmax((double)t, 1.0));
        double ld1 = log((double)t1);
        double lp0 = log((va0 ? mean0 : 1.0) + 1e-6);
        double lp1 = log((va1 ? mean1 : 1.0) + 1e-6);

        double n     = blockRed256(w0 + w1, sh);
        double sx    = blockRed256(w0 * ld0 + w1 * ld1, sh);
        double sy    = blockRed256(w0 * lp0 + w1 * lp1, sh);
        double tm    = blockRed256(((t >= 2 && t < LL) ? bs0 : 0.0) +
                                   ((t1 < LL) ? bs1 : 0.0), sh);
        double sameC = blockRed256(g_bSame[t], sh);     // exactly 256 batches
        double ncC   = blockRed256(g_bNc[t], sh);

        double nsafe = fmax(n, 1.0);
        double xm = sx / nsafe, ym = sy / nsafe;
        double num = blockRed256(w0 * (ld0 - xm) * (lp0 - ym) +
                                 w1 * (ld1 - xm) * (lp1 - ym), sh);
        double den = blockRed256(w0 * (ld0 - xm) * (ld0 - xm) +
                                 w1 * (ld1 - xm) * (ld1 - xm), sh) + 1e-8;

        if (t == 0) {
            double slope = num / den;
            double dist  = (n >= 5.0) ? (slope + 0.85) * (slope + 0.85) : 0.0;

            double ctcf = (ncC < 1.0) ? 0.0 : g_NC / (ncC + 1e-6);

            double diffC   = (double)BB * ((double)LL * LL - 3.0 * LL + 2.0) - sameC;
            double within  = g_W / fmax(sameC, 1.0);
            double between = (tm - g_W) / fmax(diffC, 1.0);
            double ratio   = within / (fabs(between) + 1e-6);
            double comp    = fmax(0.0, 1.5 - ratio);

            out[0] = (float)dist;
            out[1] = (float)ctcf;
            out[2] = (float)comp;
            out[3] = (float)(dist + 0.5 * ctcf + 0.5 * comp);
        }
    }
}

// ---------------- launch ----------------------------------------------------
extern "C" void kernel_launch(void* const* d_in, const int* in_sizes, int n_in,
                              void* d_out, int out_size) {
    const float* cm      = (const float*)d_in[0];
    const float2* logits = (const float2*)d_in[1];
    const int*   ctcf    = (const int*)d_in[2];
    float* out = (float*)d_out;

    k_prep<<<BB, 512>>>(logits, ctcf);
    k_main<<<dim3(BB, NPANEL), 256>>>(cm, out);
}